// round 9
// baseline (speedup 1.0000x reference)
#include <cuda_runtime.h>
#include <math.h>
#include <stdint.h>

#define TT 8192
#define EE 1024
#define HH 64
#define NQB 64            // 128-row query blocks
#define SPLIT 8
#define NUNIT (NQB * SPLIT)
#define KSTR 72           // attn K smem stride (floats), ==8 mod 32
#define VTSTR 136         // attn Vt smem stride (floats), ==8 mod 32
#define PSTR 36           // proj smem stride (floats), ==4 mod 32 (raw layout)

// Scratch (allocation-free: __device__ globals)
// g_q/g_k: [T][64], head-dim 8-group permuted, values RNA-rounded to tf32.
// g_vt:    [64][T], token-dim 8-group permuted, tf32-rounded (V transposed).
__device__ float g_q[TT * HH];
__device__ float g_k[TT * HH];
__device__ float g_vt[HH * TT];
__device__ float g_po[NUNIT * 128 * 64];  // partial (unnormalized) O
__device__ float g_pl[NUNIT * 128];       // partial row sums l

// ---------------------------------------------------------------------------
// helpers
// ---------------------------------------------------------------------------
__device__ __forceinline__ uint32_t tf32(float x) {
    uint32_t r;
    asm("cvt.rna.tf32.f32 %0, %1;" : "=r"(r) : "f"(x));
    return r;
}
__device__ __forceinline__ float tf32f(float x) {
    return __uint_as_float(tf32(x));
}
__device__ __forceinline__ float ex2f(float x) {
    float y;
    asm("ex2.approx.f32 %0, %1;" : "=f"(y) : "f"(x));
    return y;
}
// D += A(16x8) * B(8x8), tf32 inputs, f32 accum. Baseline PTX (sm_80+).
__device__ __forceinline__ void mma8(float* d, const uint32_t* a,
                                     uint32_t b0, uint32_t b1) {
    asm volatile(
        "mma.sync.aligned.m16n8k8.row.col.f32.tf32.tf32.f32 "
        "{%0,%1,%2,%3}, {%4,%5,%6,%7}, {%8,%9}, {%0,%1,%2,%3};"
        : "+f"(d[0]), "+f"(d[1]), "+f"(d[2]), "+f"(d[3])
        : "r"(a[0]), "r"(a[1]), "r"(a[2]), "r"(a[3]), "r"(b0), "r"(b1));
}
__device__ __forceinline__ void cpa16(uint32_t dst, const void* src) {
    asm volatile("cp.async.cg.shared.global [%0], [%1], 16;"
                 :: "r"(dst), "l"(src) : "memory");
}
#define CP_COMMIT() asm volatile("cp.async.commit_group;" ::: "memory")
#define CP_WAIT(n)  asm volatile("cp.async.wait_group " #n ";" ::: "memory")

// ---------------------------------------------------------------------------
// Projections via tf32 MMA, cp.async 4-stage ring over 32-wide e-chunks.
// CTA: 256 threads (8 warps as 4 row x 2 col), 128-row tile, warp owns 32x32.
// Raw f32 staged; RNA->tf32 conversion at fragment-load time.
// ---------------------------------------------------------------------------
#define PXSZ (128 * PSTR)
#define PWSZ (64 * PSTR)
#define PSTG (PXSZ + PWSZ)

__global__ __launch_bounds__(256, 2) void proj_mma_kernel(
    const float* __restrict__ Xq, const float* __restrict__ Xk,
    const float* __restrict__ Xv, const float* __restrict__ Wq,
    const float* __restrict__ Wk, const float* __restrict__ Wv) {
    extern __shared__ float psm[];
    const uint32_t sb = (uint32_t)__cvta_generic_to_shared(psm);

    const int which = blockIdx.y;
    const float* X = which == 0 ? Xq : (which == 1 ? Xk : Xv);
    const float* W = which == 0 ? Wq : (which == 1 ? Wk : Wv);

    const int tid  = threadIdx.x;
    const int w    = tid >> 5;
    const int lane = tid & 31;
    const int q    = lane & 3;
    const int g    = lane >> 2;
    const int wr   = w >> 1;   // 0..3 row group (32 rows)
    const int wc   = w & 1;    // 0..1 col group (32 cols)
    const int m0   = blockIdx.x * 128;

    const int xrow = tid >> 1, xpt = (tid & 1) * 4;  // X: row, 4x float4 half
    const int wrow = tid >> 2, wpt = (tid & 3) * 2;  // W: row, 2x float4 part

    // stage 32-wide chunk ec into ring buffer b
    auto issue = [&](int ec, int b) {
        uint32_t xdst = sb + (b * PSTG) * 4;
        const float* xsrc = &X[(m0 + xrow) * EE + ec * 32];
#pragma unroll
        for (int i = 0; i < 4; i++)
            cpa16(xdst + (xrow * PSTR + (xpt + i) * 4) * 4, xsrc + (xpt + i) * 4);
        uint32_t wdst = sb + (b * PSTG + PXSZ) * 4;
        const float* wsrc = &W[wrow * EE + ec * 32];
#pragma unroll
        for (int i = 0; i < 2; i++)
            cpa16(wdst + (wrow * PSTR + (wpt + i) * 4) * 4, wsrc + (wpt + i) * 4);
        CP_COMMIT();
    };

    issue(0, 0); issue(1, 1); issue(2, 2);

    float acc[2][4][4] = {};

#pragma unroll 1
    for (int ec = 0; ec < 32; ec++) {
        CP_WAIT(2);        // chunk ec has landed
        __syncthreads();

        const float* Xs = psm + (ec & 3) * PSTG;
        const float* Ws = Xs + PXSZ;

#pragma unroll
        for (int kc = 0; kc < 4; kc++) {
            uint32_t afr[2][4];
#pragma unroll
            for (int mf = 0; mf < 2; mf++) {
                const float* xr0 = &Xs[(wr * 32 + mf * 16 + g) * PSTR + kc * 8 + q];
                const float* xr1 = &Xs[(wr * 32 + mf * 16 + g + 8) * PSTR + kc * 8 + q];
                afr[mf][0] = tf32(xr0[0]);
                afr[mf][1] = tf32(xr1[0]);
                afr[mf][2] = tf32(xr0[4]);
                afr[mf][3] = tf32(xr1[4]);
            }
#pragma unroll
            for (int n = 0; n < 4; n++) {
                const float* wrp = &Ws[(wc * 32 + n * 8 + g) * PSTR + kc * 8 + q];
                uint32_t b0 = tf32(wrp[0]);
                uint32_t b1 = tf32(wrp[4]);
                mma8(acc[0][n], afr[0], b0, b1);
                mma8(acc[1][n], afr[1], b0, b1);
            }
        }
        __syncthreads();   // readers done before ring slot reuse
        if (ec + 3 < 32) issue(ec + 3, (ec + 3) & 3);
        else             CP_COMMIT();   // empty group keeps wait-count uniform
    }

    // Epilogue: tf32-rounded, permuted writes.
    if (which < 2) {
        float* O = which == 0 ? g_q : g_k;
        const int d0 = (q < 2) ? 4 * q : 4 * q - 7;      // perm8(2q)
        const int d1 = (q < 2) ? 4 * q + 2 : 4 * q - 5;  // perm8(2q+1)
#pragma unroll
        for (int mf = 0; mf < 2; mf++) {
            int r = m0 + wr * 32 + mf * 16 + g;
#pragma unroll
            for (int n = 0; n < 4; n++) {
                int cb = wc * 32 + n * 8;
                O[r * HH + cb + d0]       = tf32f(acc[mf][n][0]);
                O[r * HH + cb + d1]       = tf32f(acc[mf][n][1]);
                O[(r + 8) * HH + cb + d0] = tf32f(acc[mf][n][2]);
                O[(r + 8) * HH + cb + d1] = tf32f(acc[mf][n][3]);
            }
        }
    } else {
        // V: transposed to g_vt[h][t'], token dim permuted within 8-groups
        const int tp = (g < 4) ? 2 * g : 2 * g - 7;  // perm8(g)
#pragma unroll
        for (int mf = 0; mf < 2; mf++) {
            int t0 = m0 + wr * 32 + mf * 16 + tp;
#pragma unroll
            for (int n = 0; n < 4; n++) {
                int h0 = wc * 32 + n * 8 + 2 * q;
                g_vt[h0 * TT + t0]           = tf32f(acc[mf][n][0]);
                g_vt[(h0 + 1) * TT + t0]     = tf32f(acc[mf][n][1]);
                g_vt[h0 * TT + t0 + 8]       = tf32f(acc[mf][n][2]);
                g_vt[(h0 + 1) * TT + t0 + 8] = tf32f(acc[mf][n][3]);
            }
        }
    }
}

// ---------------------------------------------------------------------------
// Attention partial via tf32 MMA + cp.async staging.
// CTA: 128 threads (4 warps x 32 q-rows, 2 m-frags each) -> K/V smem bytes
// amortized over 2 m-frags. K double-buffered; linear split-K combine.
// ---------------------------------------------------------------------------
__global__ __launch_bounds__(128, 2) void attn_mma_kernel() {
    extern __shared__ float asmem[];
    float* Ksb[2] = {asmem, asmem + 128 * KSTR};
    float* Vts = asmem + 2 * 128 * KSTR;     // [64][VTSTR]
    const uint32_t sb = (uint32_t)__cvta_generic_to_shared(asmem);
    const uint32_t ks_u[2] = {sb, sb + 128 * KSTR * 4};
    const uint32_t vt_u = sb + 2 * 128 * KSTR * 4;

    const int tid  = threadIdx.x;
    const int w    = tid >> 5;
    const int lane = tid & 31;
    const int q    = lane & 3;
    const int g    = lane >> 2;
    const int unit = blockIdx.x;
    const int qb   = (NQB - 1) - (unit / SPLIT);  // heavy first
    const int sp   = unit % SPLIT;
    const int nkt  = qb + 1;
    const int kt0  = (sp * nkt) / SPLIT;
    const int kt1  = ((sp + 1) * nkt) / SPLIT;

    if (kt0 == kt1) {  // empty split: zero partials
        float* po = &g_po[unit * 8192 + tid * 64];
#pragma unroll
        for (int i = 0; i < 16; i++)
            *(float4*)&po[i * 4] = make_float4(0.f, 0.f, 0.f, 0.f);
        g_pl[unit * 128 + tid] = 0.0f;
        return;
    }

    // Q A-fragments straight from permuted global (already tf32-valued).
    const int rb = qb * 128 + w * 32;
    uint32_t qa[2][8][4];
#pragma unroll
    for (int mf = 0; mf < 2; mf++)
#pragma unroll
        for (int kc = 0; kc < 8; kc++) {
            float2 lo = *(const float2*)&g_q[(rb + mf * 16 + g) * HH + kc * 8 + 2 * q];
            float2 hi = *(const float2*)&g_q[(rb + mf * 16 + g + 8) * HH + kc * 8 + 2 * q];
            qa[mf][kc][0] = __float_as_uint(lo.x);
            qa[mf][kc][1] = __float_as_uint(hi.x);
            qa[mf][kc][2] = __float_as_uint(lo.y);
            qa[mf][kc][3] = __float_as_uint(hi.y);
        }

    // prefetch K(kt0) into buffer 0
    {
        const char* src = (const char*)&g_k[kt0 * 128 * HH];
#pragma unroll
        for (int i = 0; i < 16; i++) {
            int c = i * 128 + tid, row = c >> 4, part = c & 15;
            cpa16(ks_u[0] + row * (KSTR * 4) + part * 16, src + row * 256 + part * 16);
        }
        CP_COMMIT();
    }

    float oacc[2][8][4] = {};
    float lacc[2][2] = {};
    const float C = 0.18033688f;  // log2(e)/8
    const int src0 = (lane & 28) | (q >> 1);
    const int src1 = src0 + 2;
    const bool e = q & 1;
    int buf = 0;

    for (int kt = kt0; kt < kt1; kt++) {
        {   // stage Vt(kt)
            const char* src = (const char*)&g_vt[kt * 128];
#pragma unroll
            for (int i = 0; i < 16; i++) {
                int c = i * 128 + tid, h = c >> 5, part = c & 31;
                cpa16(vt_u + h * (VTSTR * 4) + part * 16,
                      src + (size_t)h * (TT * 4) + part * 16);
            }
            CP_COMMIT();
        }
        if (kt + 1 < kt1) {  // prefetch K(kt+1) into alternate buffer
            const char* src = (const char*)&g_k[(kt + 1) * 128 * HH];
#pragma unroll
            for (int i = 0; i < 16; i++) {
                int c = i * 128 + tid, row = c >> 4, part = c & 15;
                cpa16(ks_u[buf ^ 1] + row * (KSTR * 4) + part * 16,
                      src + row * 256 + part * 16);
            }
            CP_COMMIT();
            CP_WAIT(1);
        } else {
            CP_WAIT(0);
        }
        __syncthreads();

        const float* Kb = Ksb[buf];
        const bool diag = (kt == qb);
#pragma unroll 2
        for (int st = 0; st < 16; st++) {
            // 4 independent accumulator chains (2 mf x 2 kc-halves)
            float sa[2][4] = {}, sbq[2][4] = {};
#pragma unroll
            for (int kc = 0; kc < 4; kc++) {
                float2 b0 = *(const float2*)&Kb[(st * 8 + g) * KSTR + kc * 8 + 2 * q];
                uint32_t b0x = __float_as_uint(b0.x), b0y = __float_as_uint(b0.y);
                mma8(sa[0], qa[0][kc], b0x, b0y);
                mma8(sa[1], qa[1][kc], b0x, b0y);
                float2 b1 = *(const float2*)&Kb[(st * 8 + g) * KSTR + (kc + 4) * 8 + 2 * q];
                uint32_t b1x = __float_as_uint(b1.x), b1y = __float_as_uint(b1.y);
                mma8(sbq[0], qa[0][kc + 4], b1x, b1y);
                mma8(sbq[1], qa[1][kc + 4], b1x, b1y);
            }
            uint32_t pa[2][4];
#pragma unroll
            for (int mf = 0; mf < 2; mf++) {
                float p0 = ex2f((sa[mf][0] + sbq[mf][0]) * C);
                float p1 = ex2f((sa[mf][1] + sbq[mf][1]) * C);
                float p2 = ex2f((sa[mf][2] + sbq[mf][2]) * C);
                float p3 = ex2f((sa[mf][3] + sbq[mf][3]) * C);
                if (diag) {
                    int i0 = w * 32 + mf * 16 + g, i1 = i0 + 8;
                    int j0 = st * 8 + q * 2, j1 = j0 + 1;
                    if (j0 > i0) p0 = 0.0f;
                    if (j1 > i0) p1 = 0.0f;
                    if (j0 > i1) p2 = 0.0f;
                    if (j1 > i1) p3 = 0.0f;
                }
                lacc[mf][0] += p0 + p1;
                lacc[mf][1] += p2 + p3;

                // permute C-frag -> A-frag layout within quads
                float s00 = __shfl_sync(0xffffffffu, p0, src0);
                float s01 = __shfl_sync(0xffffffffu, p1, src0);
                float s02 = __shfl_sync(0xffffffffu, p0, src1);
                float s03 = __shfl_sync(0xffffffffu, p1, src1);
                float s10 = __shfl_sync(0xffffffffu, p2, src0);
                float s11 = __shfl_sync(0xffffffffu, p3, src0);
                float s12 = __shfl_sync(0xffffffffu, p2, src1);
                float s13 = __shfl_sync(0xffffffffu, p3, src1);
                pa[mf][0] = tf32(e ? s01 : s00);
                pa[mf][1] = tf32(e ? s11 : s10);
                pa[mf][2] = tf32(e ? s03 : s02);
                pa[mf][3] = tf32(e ? s13 : s12);
            }

#pragma unroll
            for (int n = 0; n < 8; n++) {
                float2 vv = *(const float2*)&Vts[(n * 8 + g) * VTSTR + st * 8 + 2 * q];
                uint32_t vx = __float_as_uint(vv.x), vy = __float_as_uint(vv.y);
                mma8(oacc[0][n], pa[0], vx, vy);
                mma8(oacc[1][n], pa[1], vx, vy);
            }
        }
        buf ^= 1;
        __syncthreads();  // before next-iter Vt overwrite
    }

    // row-sum reduce within quads; write partials for both m-frags
#pragma unroll
    for (int mf = 0; mf < 2; mf++) {
        lacc[mf][0] += __shfl_xor_sync(0xffffffffu, lacc[mf][0], 1);
        lacc[mf][0] += __shfl_xor_sync(0xffffffffu, lacc[mf][0], 2);
        lacc[mf][1] += __shfl_xor_sync(0xffffffffu, lacc[mf][1], 1);
        lacc[mf][1] += __shfl_xor_sync(0xffffffffu, lacc[mf][1], 2);
        int i0 = w * 32 + mf * 16 + g;
        if (q == 0) {
            g_pl[unit * 128 + i0]     = lacc[mf][0];
            g_pl[unit * 128 + i0 + 8] = lacc[mf][1];
        }
        float* po = &g_po[unit * 8192];
#pragma unroll
        for (int n = 0; n < 8; n++) {
            int col = n * 8 + q * 2;
            *(float2*)&po[i0 * 64 + col] = make_float2(oacc[mf][n][0], oacc[mf][n][1]);
            *(float2*)&po[(i0 + 8) * 64 + col] = make_float2(oacc[mf][n][2], oacc[mf][n][3]);
        }
    }
}

// ---------------------------------------------------------------------------
// Combine: out = (sum_sp O_sp) / (sum_sp l_sp)
// ---------------------------------------------------------------------------
__global__ __launch_bounds__(128) void combine_kernel(float* __restrict__ out) {
    const int qb = blockIdx.x;
    const int r  = threadIdx.x;
    const int ub = (NQB - 1 - qb) * SPLIT;

    float L = 0.0f;
#pragma unroll
    for (int s = 0; s < SPLIT; s++) L += g_pl[(ub + s) * 128 + r];
    float inv = 1.0f / L;

#pragma unroll
    for (int c4 = 0; c4 < 16; c4++) {
        float4 acc = make_float4(0.f, 0.f, 0.f, 0.f);
#pragma unroll
        for (int s = 0; s < SPLIT; s++) {
            float4 v = *(const float4*)&g_po[(ub + s) * 8192 + r * 64 + c4 * 4];
            acc.x += v.x; acc.y += v.y; acc.z += v.z; acc.w += v.w;
        }
        acc.x *= inv; acc.y *= inv; acc.z *= inv; acc.w *= inv;
        *(float4*)&out[(qb * 128 + r) * HH + c4 * 4] = acc;
    }
}

// ---------------------------------------------------------------------------
extern "C" void kernel_launch(void* const* d_in, const int* in_sizes, int n_in,
                              void* d_out, int out_size) {
    const float* Xq = (const float*)d_in[0];
    const float* Xk = (const float*)d_in[1];
    const float* Xv = (const float*)d_in[2];
    // d_in[3] = mask (causal, implied analytically) -- unused
    const float* Wq = (const float*)d_in[4];
    const float* Wk = (const float*)d_in[5];
    const float* Wv = (const float*)d_in[6];
    float* out = (float*)d_out;

    const int proj_smem = 4 * PSTG * (int)sizeof(float);
    const int attn_smem = (2 * 128 * KSTR + 64 * VTSTR) * (int)sizeof(float);
    cudaFuncSetAttribute(proj_mma_kernel,
                         cudaFuncAttributeMaxDynamicSharedMemorySize, proj_smem);
    cudaFuncSetAttribute(attn_mma_kernel,
                         cudaFuncAttributeMaxDynamicSharedMemorySize, attn_smem);

    dim3 pg(TT / 128, 3);
    proj_mma_kernel<<<pg, 256, proj_smem>>>(Xq, Xk, Xv, Wq, Wk, Wv);
    attn_mma_kernel<<<NUNIT, 128, attn_smem>>>();
    combine_kernel<<<NQB, 128>>>(out);
}

// round 10
// speedup vs baseline: 1.0663x; 1.0663x over previous
#include <cuda_runtime.h>
#include <math.h>
#include <stdint.h>

#define TT 8192
#define EE 1024
#define HH 64
#define NQB 64            // 128-row query blocks
#define SPLIT 8
#define NUNIT (NQB * SPLIT)
#define KSTR 72           // attn K smem stride (floats), ==8 mod 32
#define VTSTR 136         // attn Vt smem stride (floats), ==8 mod 32
#define PSTR 68           // proj smem stride (floats), ==4 mod 32 (raw layout)

// Scratch (allocation-free: __device__ globals)
// g_q/g_k: [T][64], head-dim 8-group permuted, values RNA-rounded to tf32.
// g_vt:    [64][T], token-dim 8-group permuted, tf32-rounded (V transposed).
__device__ float g_q[TT * HH];
__device__ float g_k[TT * HH];
__device__ float g_vt[HH * TT];
__device__ float g_po[NUNIT * 128 * 64];  // partial (unnormalized) O
__device__ float g_pl[NUNIT * 128];       // partial row sums l

// ---------------------------------------------------------------------------
// helpers
// ---------------------------------------------------------------------------
__device__ __forceinline__ uint32_t tf32(float x) {
    uint32_t r;
    asm("cvt.rna.tf32.f32 %0, %1;" : "=r"(r) : "f"(x));
    return r;
}
__device__ __forceinline__ float tf32f(float x) {
    return __uint_as_float(tf32(x));
}
__device__ __forceinline__ float ex2f(float x) {
    float y;
    asm("ex2.approx.f32 %0, %1;" : "=f"(y) : "f"(x));
    return y;
}
// D += A(16x8) * B(8x8), tf32 inputs, f32 accum. Baseline PTX (sm_80+).
__device__ __forceinline__ void mma8(float* d, const uint32_t* a,
                                     uint32_t b0, uint32_t b1) {
    asm volatile(
        "mma.sync.aligned.m16n8k8.row.col.f32.tf32.tf32.f32 "
        "{%0,%1,%2,%3}, {%4,%5,%6,%7}, {%8,%9}, {%0,%1,%2,%3};"
        : "+f"(d[0]), "+f"(d[1]), "+f"(d[2]), "+f"(d[3])
        : "r"(a[0]), "r"(a[1]), "r"(a[2]), "r"(a[3]), "r"(b0), "r"(b1));
}
__device__ __forceinline__ void cpa16(uint32_t dst, const void* src) {
    asm volatile("cp.async.cg.shared.global [%0], [%1], 16;"
                 :: "r"(dst), "l"(src) : "memory");
}
#define CP_COMMIT() asm volatile("cp.async.commit_group;" ::: "memory")
#define CP_WAIT(n)  asm volatile("cp.async.wait_group " #n ";" ::: "memory")

// ---------------------------------------------------------------------------
// Projections via tf32 MMA, cp.async double-buffered over 64-wide e-chunks.
// 64-row tiles -> 384 blocks, 3 CTAs/SM (load balance). 256 threads,
// 8 warps as 2 row x 4 col; warp owns 32x16. Raw f32 staged; cvt at frag load.
// ---------------------------------------------------------------------------
#define PXSZ (64 * PSTR)
#define PSTG (2 * PXSZ)    // X tile + W tile

__global__ __launch_bounds__(256, 3) void proj_mma_kernel(
    const float* __restrict__ Xq, const float* __restrict__ Xk,
    const float* __restrict__ Xv, const float* __restrict__ Wq,
    const float* __restrict__ Wk, const float* __restrict__ Wv) {
    extern __shared__ float psm[];
    const uint32_t sb = (uint32_t)__cvta_generic_to_shared(psm);

    const int which = blockIdx.y;
    const float* X = which == 0 ? Xq : (which == 1 ? Xk : Xv);
    const float* W = which == 0 ? Wq : (which == 1 ? Wk : Wv);

    const int tid  = threadIdx.x;
    const int w    = tid >> 5;
    const int lane = tid & 31;
    const int q    = lane & 3;
    const int g    = lane >> 2;
    const int wr   = w >> 2;   // 0..1 row group (32 rows)
    const int wc   = w & 3;    // 0..3 col group (16 cols)
    const int m0   = blockIdx.x * 64;

    const int srow = tid >> 2;        // 0..63
    const int spt  = tid & 3;         // 4 float4 chunks, stride 16 floats

    // stage chunk ec into buffer b
    auto issue = [&](int ec, int b) {
        uint32_t xdst = sb + (b * PSTG) * 4;
        const float* xsrc = &X[(m0 + srow) * EE + ec * 64];
        uint32_t wdst = xdst + PXSZ * 4;
        const float* wsrc = &W[srow * EE + ec * 64];
#pragma unroll
        for (int i = 0; i < 4; i++) {
            int c4 = spt + i * 4;
            cpa16(xdst + (srow * PSTR + c4 * 4) * 4, xsrc + c4 * 4);
            cpa16(wdst + (srow * PSTR + c4 * 4) * 4, wsrc + c4 * 4);
        }
        CP_COMMIT();
    };

    issue(0, 0);

    float acc[2][2][4] = {};
    int buf = 0;

#pragma unroll 1
    for (int ec = 0; ec < 16; ec++) {
        if (ec < 15) { issue(ec + 1, buf ^ 1); CP_WAIT(1); }
        else         { CP_WAIT(0); }
        __syncthreads();

        const float* Xs = psm + buf * PSTG;
        const float* Ws = Xs + PXSZ;

#pragma unroll
        for (int kc = 0; kc < 8; kc++) {
            uint32_t afr[2][4];
#pragma unroll
            for (int mf = 0; mf < 2; mf++) {
                const float* xr0 = &Xs[(wr * 32 + mf * 16 + g) * PSTR + kc * 8 + q];
                const float* xr1 = &Xs[(wr * 32 + mf * 16 + g + 8) * PSTR + kc * 8 + q];
                afr[mf][0] = tf32(xr0[0]);
                afr[mf][1] = tf32(xr1[0]);
                afr[mf][2] = tf32(xr0[4]);
                afr[mf][3] = tf32(xr1[4]);
            }
#pragma unroll
            for (int n = 0; n < 2; n++) {
                const float* wrp = &Ws[(wc * 16 + n * 8 + g) * PSTR + kc * 8 + q];
                uint32_t b0 = tf32(wrp[0]);
                uint32_t b1 = tf32(wrp[4]);
                mma8(acc[0][n], afr[0], b0, b1);
                mma8(acc[1][n], afr[1], b0, b1);
            }
        }
        __syncthreads();   // readers done before next issue overwrites buf
        buf ^= 1;
    }

    // Epilogue: tf32-rounded, permuted writes.
    if (which < 2) {
        float* O = which == 0 ? g_q : g_k;
        const int d0 = (q < 2) ? 4 * q : 4 * q - 7;      // perm8(2q)
        const int d1 = (q < 2) ? 4 * q + 2 : 4 * q - 5;  // perm8(2q+1)
#pragma unroll
        for (int mf = 0; mf < 2; mf++) {
            int r = m0 + wr * 32 + mf * 16 + g;
#pragma unroll
            for (int n = 0; n < 2; n++) {
                int cb = wc * 16 + n * 8;
                O[r * HH + cb + d0]       = tf32f(acc[mf][n][0]);
                O[r * HH + cb + d1]       = tf32f(acc[mf][n][1]);
                O[(r + 8) * HH + cb + d0] = tf32f(acc[mf][n][2]);
                O[(r + 8) * HH + cb + d1] = tf32f(acc[mf][n][3]);
            }
        }
    } else {
        // V: transposed to g_vt[h][t'], token dim permuted within 8-groups
        const int tp = (g < 4) ? 2 * g : 2 * g - 7;  // perm8(g)
#pragma unroll
        for (int mf = 0; mf < 2; mf++) {
            int t0 = m0 + wr * 32 + mf * 16 + tp;
#pragma unroll
            for (int n = 0; n < 2; n++) {
                int h0 = wc * 16 + n * 8 + 2 * q;
                g_vt[h0 * TT + t0]           = tf32f(acc[mf][n][0]);
                g_vt[(h0 + 1) * TT + t0]     = tf32f(acc[mf][n][1]);
                g_vt[h0 * TT + t0 + 8]       = tf32f(acc[mf][n][2]);
                g_vt[(h0 + 1) * TT + t0 + 8] = tf32f(acc[mf][n][3]);
            }
        }
    }
}

// ---------------------------------------------------------------------------
// Attention partial via tf32 MMA + cp.async staging (round-8 proven config:
// 256 threads, 8 warps x 16 q-rows). K double-buffered; linear combine.
// ---------------------------------------------------------------------------
__global__ __launch_bounds__(256, 2) void attn_mma_kernel() {
    extern __shared__ float asmem[];
    float* Ksb[2] = {asmem, asmem + 128 * KSTR};
    float* Vts = asmem + 2 * 128 * KSTR;     // [64][VTSTR]
    const uint32_t sb = (uint32_t)__cvta_generic_to_shared(asmem);
    const uint32_t ks_u[2] = {sb, sb + 128 * KSTR * 4};
    const uint32_t vt_u = sb + 2 * 128 * KSTR * 4;

    const int tid  = threadIdx.x;
    const int w    = tid >> 5;
    const int lane = tid & 31;
    const int q    = lane & 3;
    const int g    = lane >> 2;
    const int unit = blockIdx.x;
    const int qb   = (NQB - 1) - (unit / SPLIT);  // heavy first
    const int sp   = unit % SPLIT;
    const int nkt  = qb + 1;
    const int kt0  = (sp * nkt) / SPLIT;
    const int kt1  = ((sp + 1) * nkt) / SPLIT;

    if (kt0 == kt1) {  // empty split: zero partials
        float* po = &g_po[unit * 8192 + (tid >> 1) * 64 + (tid & 1) * 32];
#pragma unroll
        for (int i = 0; i < 8; i++)
            *(float4*)&po[i * 4] = make_float4(0.f, 0.f, 0.f, 0.f);
        if (tid < 128) g_pl[unit * 128 + tid] = 0.0f;
        return;
    }

    // Q A-fragments straight from permuted global (already tf32-valued).
    const int r0 = qb * 128 + w * 16 + g;
    uint32_t qa[8][4];
#pragma unroll
    for (int kc = 0; kc < 8; kc++) {
        float2 lo = *(const float2*)&g_q[r0 * HH + kc * 8 + 2 * q];
        float2 hi = *(const float2*)&g_q[(r0 + 8) * HH + kc * 8 + 2 * q];
        qa[kc][0] = __float_as_uint(lo.x);
        qa[kc][1] = __float_as_uint(hi.x);
        qa[kc][2] = __float_as_uint(lo.y);
        qa[kc][3] = __float_as_uint(hi.y);
    }

    // prefetch K(kt0) into buffer 0
    {
        const char* src = (const char*)&g_k[kt0 * 128 * HH];
#pragma unroll
        for (int i = 0; i < 8; i++) {
            int c = i * 256 + tid, row = c >> 4, part = c & 15;
            cpa16(ks_u[0] + row * (KSTR * 4) + part * 16, src + row * 256 + part * 16);
        }
        CP_COMMIT();
    }

    float oacc[8][4] = {};
    float lacc0 = 0.0f, lacc1 = 0.0f;
    const float C = 0.18033688f;  // log2(e)/8
    const int i0 = w * 16 + g, i1 = i0 + 8;
    const int src0 = (lane & 28) | (q >> 1);
    const int src1 = src0 + 2;
    const bool e = q & 1;
    int buf = 0;

    for (int kt = kt0; kt < kt1; kt++) {
        {   // stage Vt(kt)
            const char* src = (const char*)&g_vt[kt * 128];
#pragma unroll
            for (int i = 0; i < 8; i++) {
                int c = i * 256 + tid, h = c >> 5, part = c & 31;
                cpa16(vt_u + h * (VTSTR * 4) + part * 16,
                      src + (size_t)h * (TT * 4) + part * 16);
            }
            CP_COMMIT();
        }
        if (kt + 1 < kt1) {  // prefetch K(kt+1) into alternate buffer
            const char* src = (const char*)&g_k[(kt + 1) * 128 * HH];
#pragma unroll
            for (int i = 0; i < 8; i++) {
                int c = i * 256 + tid, row = c >> 4, part = c & 15;
                cpa16(ks_u[buf ^ 1] + row * (KSTR * 4) + part * 16,
                      src + row * 256 + part * 16);
            }
            CP_COMMIT();
            CP_WAIT(1);
        } else {
            CP_WAIT(0);
        }
        __syncthreads();

        const float* Kb = Ksb[buf];
        const bool diag = (kt == qb);
#pragma unroll 2
        for (int st = 0; st < 16; st++) {
            // two independent accumulator sets halve the HMMA dep chain
            float sa[4] = {0.f, 0.f, 0.f, 0.f};
            float sbq[4] = {0.f, 0.f, 0.f, 0.f};
#pragma unroll
            for (int kc = 0; kc < 4; kc++) {
                float2 b0 = *(const float2*)&Kb[(st * 8 + g) * KSTR + kc * 8 + 2 * q];
                mma8(sa, qa[kc], __float_as_uint(b0.x), __float_as_uint(b0.y));
                float2 b1 = *(const float2*)&Kb[(st * 8 + g) * KSTR + (kc + 4) * 8 + 2 * q];
                mma8(sbq, qa[kc + 4], __float_as_uint(b1.x), __float_as_uint(b1.y));
            }
            float p0 = ex2f((sa[0] + sbq[0]) * C);
            float p1 = ex2f((sa[1] + sbq[1]) * C);
            float p2 = ex2f((sa[2] + sbq[2]) * C);
            float p3 = ex2f((sa[3] + sbq[3]) * C);
            if (diag) {
                int j0 = st * 8 + q * 2, j1 = j0 + 1;
                if (j0 > i0) p0 = 0.0f;
                if (j1 > i0) p1 = 0.0f;
                if (j0 > i1) p2 = 0.0f;
                if (j1 > i1) p3 = 0.0f;
            }
            lacc0 += p0 + p1;
            lacc1 += p2 + p3;

            // permute C-frag -> A-frag layout within quads
            float s00 = __shfl_sync(0xffffffffu, p0, src0);
            float s01 = __shfl_sync(0xffffffffu, p1, src0);
            float s02 = __shfl_sync(0xffffffffu, p0, src1);
            float s03 = __shfl_sync(0xffffffffu, p1, src1);
            float s10 = __shfl_sync(0xffffffffu, p2, src0);
            float s11 = __shfl_sync(0xffffffffu, p3, src0);
            float s12 = __shfl_sync(0xffffffffu, p2, src1);
            float s13 = __shfl_sync(0xffffffffu, p3, src1);
            uint32_t pa[4];
            pa[0] = tf32(e ? s01 : s00);
            pa[1] = tf32(e ? s11 : s10);
            pa[2] = tf32(e ? s03 : s02);
            pa[3] = tf32(e ? s13 : s12);

#pragma unroll
            for (int n = 0; n < 8; n++) {
                float2 vv = *(const float2*)&Vts[(n * 8 + g) * VTSTR + st * 8 + 2 * q];
                mma8(oacc[n], pa, __float_as_uint(vv.x), __float_as_uint(vv.y));
            }
        }
        buf ^= 1;
        __syncthreads();  // before next-iter Vt overwrite
    }

    lacc0 += __shfl_xor_sync(0xffffffffu, lacc0, 1);
    lacc0 += __shfl_xor_sync(0xffffffffu, lacc0, 2);
    lacc1 += __shfl_xor_sync(0xffffffffu, lacc1, 1);
    lacc1 += __shfl_xor_sync(0xffffffffu, lacc1, 2);
    if (q == 0) {
        g_pl[unit * 128 + i0] = lacc0;
        g_pl[unit * 128 + i1] = lacc1;
    }

    float* po = &g_po[unit * 8192];
#pragma unroll
    for (int n = 0; n < 8; n++) {
        int col = n * 8 + q * 2;
        *(float2*)&po[i0 * 64 + col] = make_float2(oacc[n][0], oacc[n][1]);
        *(float2*)&po[i1 * 64 + col] = make_float2(oacc[n][2], oacc[n][3]);
    }
}

// ---------------------------------------------------------------------------
// Combine: out = (sum_sp O_sp) / (sum_sp l_sp)
// ---------------------------------------------------------------------------
__global__ __launch_bounds__(128) void combine_kernel(float* __restrict__ out) {
    const int qb = blockIdx.x;
    const int r  = threadIdx.x;
    const int ub = (NQB - 1 - qb) * SPLIT;

    float L = 0.0f;
#pragma unroll
    for (int s = 0; s < SPLIT; s++) L += g_pl[(ub + s) * 128 + r];
    float inv = 1.0f / L;

#pragma unroll
    for (int c4 = 0; c4 < 16; c4++) {
        float4 acc = make_float4(0.f, 0.f, 0.f, 0.f);
#pragma unroll
        for (int s = 0; s < SPLIT; s++) {
            float4 v = *(const float4*)&g_po[(ub + s) * 8192 + r * 64 + c4 * 4];
            acc.x += v.x; acc.y += v.y; acc.z += v.z; acc.w += v.w;
        }
        acc.x *= inv; acc.y *= inv; acc.z *= inv; acc.w *= inv;
        *(float4*)&out[(qb * 128 + r) * HH + c4 * 4] = acc;
    }
}

// ---------------------------------------------------------------------------
extern "C" void kernel_launch(void* const* d_in, const int* in_sizes, int n_in,
                              void* d_out, int out_size) {
    const float* Xq = (const float*)d_in[0];
    const float* Xk = (const float*)d_in[1];
    const float* Xv = (const float*)d_in[2];
    // d_in[3] = mask (causal, implied analytically) -- unused
    const float* Wq = (const float*)d_in[4];
    const float* Wk = (const float*)d_in[5];
    const float* Wv = (const float*)d_in[6];
    float* out = (float*)d_out;

    const int proj_smem = 2 * PSTG * (int)sizeof(float);
    const int attn_smem = (2 * 128 * KSTR + 64 * VTSTR) * (int)sizeof(float);
    cudaFuncSetAttribute(proj_mma_kernel,
                         cudaFuncAttributeMaxDynamicSharedMemorySize, proj_smem);
    cudaFuncSetAttribute(attn_mma_kernel,
                         cudaFuncAttributeMaxDynamicSharedMemorySize, attn_smem);

    dim3 pg(TT / 64, 3);
    proj_mma_kernel<<<pg, 256, proj_smem>>>(Xq, Xk, Xv, Wq, Wk, Wv);
    attn_mma_kernel<<<NUNIT, 256, attn_smem>>>();
    combine_kernel<<<NQB, 128>>>(out);
}

// round 11
// speedup vs baseline: 1.4781x; 1.3862x over previous
#include <cuda_runtime.h>
#include <cuda_fp16.h>
#include <math.h>
#include <stdint.h>

#define TT 8192
#define EE 1024
#define HH 64
#define NQB 64            // 128-row query blocks
#define SPLIT 8
#define NUNIT (NQB * SPLIT)
#define PSTR 68           // proj smem stride (floats), ==4 mod 32 (raw layout)
#define KSTRH 80          // attn K smem stride (halves, 160B) ==16 mod 64
#define VTSTRH 144        // attn Vt smem stride (halves, 288B) ==16 mod 64

// Scratch (allocation-free: __device__ globals)
// g_q/g_k: fp16 [T][64], head-dim PAIRS permuted within 16-groups
//          (pair j -> slot perm8(j)) so f16 A/B frags load as single 8B LDS.
// g_vt:    fp16 [64][T], V transposed, token pairs permuted likewise.
__device__ __half g_q[TT * HH];
__device__ __half g_k[TT * HH];
__device__ __half g_vt[HH * TT];
__device__ float  g_po[NUNIT * 128 * 64];  // partial (unnormalized) O
__device__ float  g_pl[NUNIT * 128];       // partial row sums l

// ---------------------------------------------------------------------------
// helpers
// ---------------------------------------------------------------------------
__device__ __forceinline__ uint32_t tf32(float x) {
    uint32_t r;
    asm("cvt.rna.tf32.f32 %0, %1;" : "=r"(r) : "f"(x));
    return r;
}
__device__ __forceinline__ float ex2f(float x) {
    float y;
    asm("ex2.approx.f32 %0, %1;" : "=f"(y) : "f"(x));
    return y;
}
__device__ __forceinline__ uint32_t packh2(float a, float b) {
    __half2 h = __floats2half2_rn(a, b);
    return *(uint32_t*)&h;
}
// tf32: D += A(16x8) * B(8x8)
__device__ __forceinline__ void mma8(float* d, const uint32_t* a,
                                     uint32_t b0, uint32_t b1) {
    asm volatile(
        "mma.sync.aligned.m16n8k8.row.col.f32.tf32.tf32.f32 "
        "{%0,%1,%2,%3}, {%4,%5,%6,%7}, {%8,%9}, {%0,%1,%2,%3};"
        : "+f"(d[0]), "+f"(d[1]), "+f"(d[2]), "+f"(d[3])
        : "r"(a[0]), "r"(a[1]), "r"(a[2]), "r"(a[3]), "r"(b0), "r"(b1));
}
// f16: D += A(16x16) * B(16x8), f32 accum
__device__ __forceinline__ void mma16(float* d, const uint32_t* a,
                                      uint32_t b0, uint32_t b1) {
    asm volatile(
        "mma.sync.aligned.m16n8k16.row.col.f32.f16.f16.f32 "
        "{%0,%1,%2,%3}, {%4,%5,%6,%7}, {%8,%9}, {%0,%1,%2,%3};"
        : "+f"(d[0]), "+f"(d[1]), "+f"(d[2]), "+f"(d[3])
        : "r"(a[0]), "r"(a[1]), "r"(a[2]), "r"(a[3]), "r"(b0), "r"(b1));
}
__device__ __forceinline__ void cpa16(uint32_t dst, const void* src) {
    asm volatile("cp.async.cg.shared.global [%0], [%1], 16;"
                 :: "r"(dst), "l"(src) : "memory");
}
#define CP_COMMIT() asm volatile("cp.async.commit_group;" ::: "memory")
#define CP_WAIT(n)  asm volatile("cp.async.wait_group " #n ";" ::: "memory")

// ---------------------------------------------------------------------------
// Projections via tf32 MMA (round-8 proven config), fp16 pair-permuted outputs.
// CTA: 256 threads (8 warps as 4 row x 2 col), 128-row tile, warp owns 32x32.
// ---------------------------------------------------------------------------
#define PXSZ (128 * PSTR)
#define PWSZ (64 * PSTR)
#define PSTG (PXSZ + PWSZ)

__global__ __launch_bounds__(256, 2) void proj_mma_kernel(
    const float* __restrict__ Xq, const float* __restrict__ Xk,
    const float* __restrict__ Xv, const float* __restrict__ Wq,
    const float* __restrict__ Wk, const float* __restrict__ Wv) {
    extern __shared__ float psm[];
    const uint32_t sb = (uint32_t)__cvta_generic_to_shared(psm);

    const int which = blockIdx.y;
    const float* X = which == 0 ? Xq : (which == 1 ? Xk : Xv);
    const float* W = which == 0 ? Wq : (which == 1 ? Wk : Wv);

    const int tid  = threadIdx.x;
    const int w    = tid >> 5;
    const int lane = tid & 31;
    const int q    = lane & 3;
    const int g    = lane >> 2;
    const int wr   = w >> 1;   // 0..3 row group (32 rows)
    const int wc   = w & 1;    // 0..1 col group (32 cols)
    const int m0   = blockIdx.x * 128;

    const int srow = tid >> 4;       // 0..15
    const int spart = tid & 15;      // 16B chunk within 64-float row

    auto issue = [&](int ec, int b) {
        uint32_t xdst = sb + (b * PSTG) * 4;
#pragma unroll
        for (int i = 0; i < 8; i++) {
            int row = i * 16 + srow;
            cpa16(xdst + (row * PSTR + spart * 4) * 4,
                  &X[(m0 + row) * EE + ec * 64 + spart * 4]);
        }
        uint32_t wdst = sb + (b * PSTG + PXSZ) * 4;
#pragma unroll
        for (int i = 0; i < 4; i++) {
            int row = i * 16 + srow;
            cpa16(wdst + (row * PSTR + spart * 4) * 4,
                  &W[row * EE + ec * 64 + spart * 4]);
        }
        CP_COMMIT();
    };

    issue(0, 0);

    float acc[2][4][4] = {};
    int buf = 0;

#pragma unroll 1
    for (int ec = 0; ec < 16; ec++) {
        if (ec < 15) { issue(ec + 1, buf ^ 1); CP_WAIT(1); }
        else         { CP_WAIT(0); }
        __syncthreads();

        const float* Xs = psm + buf * PSTG;
        const float* Ws = Xs + PXSZ;

#pragma unroll
        for (int kc = 0; kc < 8; kc++) {
            uint32_t afr[2][4];
#pragma unroll
            for (int mf = 0; mf < 2; mf++) {
                const float* xr0 = &Xs[(wr * 32 + mf * 16 + g) * PSTR + kc * 8 + q];
                const float* xr1 = &Xs[(wr * 32 + mf * 16 + g + 8) * PSTR + kc * 8 + q];
                afr[mf][0] = tf32(xr0[0]);
                afr[mf][1] = tf32(xr1[0]);
                afr[mf][2] = tf32(xr0[4]);
                afr[mf][3] = tf32(xr1[4]);
            }
#pragma unroll
            for (int n = 0; n < 4; n++) {
                const float* wrp = &Ws[(wc * 32 + n * 8 + g) * PSTR + kc * 8 + q];
                uint32_t b0 = tf32(wrp[0]);
                uint32_t b1 = tf32(wrp[4]);
                mma8(acc[0][n], afr[0], b0, b1);
                mma8(acc[1][n], afr[1], b0, b1);
            }
        }
        __syncthreads();
        buf ^= 1;
    }

    // Epilogue: fp16, pair-permuted writes.
    if (which < 2) {
        __half* O = which == 0 ? g_q : g_k;
#pragma unroll
        for (int mf = 0; mf < 2; mf++) {
            int r = m0 + wr * 32 + mf * 16 + g;
#pragma unroll
            for (int n = 0; n < 4; n++) {
                int blk = wc * 2 + (n >> 1);         // 16-col block
                int j   = (n & 1) * 4 + q;           // pair index in block
                int s   = j < 4 ? 2 * j : 2 * j - 7; // perm8
                int off = blk * 16 + 2 * s;
                *(__half2*)&O[r * HH + off] =
                    __floats2half2_rn(acc[mf][n][0], acc[mf][n][1]);
                *(__half2*)&O[(r + 8) * HH + off] =
                    __floats2half2_rn(acc[mf][n][2], acc[mf][n][3]);
            }
        }
    } else {
        // V -> g_vt[h][t], token pairs permuted within 16-token blocks.
#pragma unroll
        for (int mf = 0; mf < 2; mf++) {
            int tbase = m0 + wr * 32 + mf * 16;   // 16-token block start
#pragma unroll
            for (int n = 0; n < 4; n++) {
                float n0 = __shfl_down_sync(0xffffffffu, acc[mf][n][0], 4);
                float n1 = __shfl_down_sync(0xffffffffu, acc[mf][n][1], 4);
                float n2 = __shfl_down_sync(0xffffffffu, acc[mf][n][2], 4);
                float n3 = __shfl_down_sync(0xffffffffu, acc[mf][n][3], 4);
                if (!(g & 1)) {
                    int h0 = wc * 32 + n * 8 + 2 * q;
                    // tokens (g,g+1) -> slot g (pos 2g); (g+8,g+9) -> slot g+1
                    *(__half2*)&g_vt[h0 * TT + tbase + 2 * g] =
                        __floats2half2_rn(acc[mf][n][0], n0);
                    *(__half2*)&g_vt[h0 * TT + tbase + 2 * g + 2] =
                        __floats2half2_rn(acc[mf][n][2], n2);
                    *(__half2*)&g_vt[(h0 + 1) * TT + tbase + 2 * g] =
                        __floats2half2_rn(acc[mf][n][1], n1);
                    *(__half2*)&g_vt[(h0 + 1) * TT + tbase + 2 * g + 2] =
                        __floats2half2_rn(acc[mf][n][3], n3);
                }
            }
        }
    }
}

// ---------------------------------------------------------------------------
// Attention partial via f16 m16n8k16 MMA. 256 threads, 8 warps x 16 q-rows.
// K and Vt both double-buffered (one commit group / tile, one barrier / tile).
// No shuffles: S C-frags pack directly into PV A-frags.
// ---------------------------------------------------------------------------
#define KBUF (128 * KSTRH * 2)   // bytes
#define VBUF (64 * VTSTRH * 2)   // bytes

__global__ __launch_bounds__(256, 2) void attn_mma_kernel() {
    extern __shared__ char asm_b[];
    const uint32_t sb = (uint32_t)__cvta_generic_to_shared(asm_b);
    const uint32_t ks_u[2] = {sb, sb + KBUF};
    const uint32_t vt_u[2] = {sb + 2 * KBUF, sb + 2 * KBUF + VBUF};

    const int tid  = threadIdx.x;
    const int w    = tid >> 5;
    const int lane = tid & 31;
    const int q    = lane & 3;
    const int g    = lane >> 2;
    const int unit = blockIdx.x;
    const int qb   = (NQB - 1) - (unit / SPLIT);  // heavy first
    const int sp   = unit % SPLIT;
    const int nkt  = qb + 1;
    const int kt0  = (sp * nkt) / SPLIT;
    const int kt1  = ((sp + 1) * nkt) / SPLIT;

    if (kt0 == kt1) {  // empty split: zero partials
        float* po = &g_po[unit * 8192 + (tid >> 1) * 64 + (tid & 1) * 32];
#pragma unroll
        for (int i = 0; i < 8; i++)
            *(float4*)&po[i * 4] = make_float4(0.f, 0.f, 0.f, 0.f);
        if (tid < 128) g_pl[unit * 128 + tid] = 0.0f;
        return;
    }

    // stage K(kt) + Vt(kt) into buffer b (single commit group)
    auto issueKV = [&](int kt, int b) {
#pragma unroll
        for (int i = 0; i < 4; i++) {   // K: 128 rows x 8 chunks
            int c = i * 256 + tid, row = c >> 3, part = c & 7;
            cpa16(ks_u[b] + row * (KSTRH * 2) + part * 16,
                  (const char*)(g_k + (size_t)kt * 128 * HH) + row * 128 + part * 16);
        }
#pragma unroll
        for (int i = 0; i < 4; i++) {   // Vt: 64 rows x 16 chunks
            int c = i * 256 + tid, row = c >> 4, part = c & 15;
            cpa16(vt_u[b] + row * (VTSTRH * 2) + part * 16,
                  (const char*)(g_vt + (size_t)row * TT + kt * 128) + part * 16);
        }
        CP_COMMIT();
    };

    // Q A-fragments (fp16, pair-permuted in gmem -> single 8B loads)
    const int r0 = qb * 128 + w * 16 + g;
    uint32_t qa[4][4];
#pragma unroll
    for (int kc = 0; kc < 4; kc++) {
        uint2 lo = *(const uint2*)&g_q[r0 * HH + kc * 16 + 4 * q];
        uint2 hi = *(const uint2*)&g_q[(r0 + 8) * HH + kc * 16 + 4 * q];
        qa[kc][0] = lo.x; qa[kc][1] = hi.x; qa[kc][2] = lo.y; qa[kc][3] = hi.y;
    }

    issueKV(kt0, 0);

    float oacc[8][4] = {};
    float lacc0 = 0.0f, lacc1 = 0.0f;
    const float C = 0.18033688f;  // log2(e)/8
    const int i0 = w * 16 + g, i1 = i0 + 8;
    int buf = 0;

    for (int kt = kt0; kt < kt1; kt++) {
        CP_WAIT(0);
        __syncthreads();   // data ready everywhere; prior readers of buf^1 done
        if (kt + 1 < kt1) issueKV(kt + 1, buf ^ 1);

        const __half* Kb = (const __half*)(asm_b + (buf ? KBUF : 0));
        const __half* Vb = (const __half*)(asm_b + 2 * KBUF + (buf ? VBUF : 0));
        const bool diag = (kt == qb);

#pragma unroll 2
        for (int kc2 = 0; kc2 < 8; kc2++) {
            const int st0 = 2 * kc2, st1 = st0 + 1;
            float s0[4] = {0.f, 0.f, 0.f, 0.f};
            float s1[4] = {0.f, 0.f, 0.f, 0.f};
#pragma unroll
            for (int kc = 0; kc < 4; kc++) {
                uint2 kb0 = *(const uint2*)&Kb[(st0 * 8 + g) * KSTRH + kc * 16 + 4 * q];
                uint2 kb1 = *(const uint2*)&Kb[(st1 * 8 + g) * KSTRH + kc * 16 + 4 * q];
                mma16(s0, qa[kc], kb0.x, kb0.y);
                mma16(s1, qa[kc], kb1.x, kb1.y);
            }
            float p00 = ex2f(s0[0] * C), p01 = ex2f(s0[1] * C);
            float p02 = ex2f(s0[2] * C), p03 = ex2f(s0[3] * C);
            float p10 = ex2f(s1[0] * C), p11 = ex2f(s1[1] * C);
            float p12 = ex2f(s1[2] * C), p13 = ex2f(s1[3] * C);
            if (diag) {
                int ja = st0 * 8 + 2 * q, jb = st1 * 8 + 2 * q;
                if (ja > i0)     p00 = 0.0f;
                if (ja + 1 > i0) p01 = 0.0f;
                if (ja > i1)     p02 = 0.0f;
                if (ja + 1 > i1) p03 = 0.0f;
                if (jb > i0)     p10 = 0.0f;
                if (jb + 1 > i0) p11 = 0.0f;
                if (jb > i1)     p12 = 0.0f;
                if (jb + 1 > i1) p13 = 0.0f;
            }
            lacc0 += p00 + p01 + p10 + p11;
            lacc1 += p02 + p03 + p12 + p13;

            // PV A-frag: direct pack, no shuffles (f16 pair layout == C layout)
            uint32_t pa[4];
            pa[0] = packh2(p00, p01);   // row g,   k 0-7  (st0)
            pa[1] = packh2(p02, p03);   // row g+8, k 0-7  (st0)
            pa[2] = packh2(p10, p11);   // row g,   k 8-15 (st1)
            pa[3] = packh2(p12, p13);   // row g+8, k 8-15 (st1)

#pragma unroll
            for (int n = 0; n < 8; n++) {
                uint2 vb = *(const uint2*)&Vb[(n * 8 + g) * VTSTRH + kc2 * 16 + 4 * q];
                mma16(oacc[n], pa, vb.x, vb.y);
            }
        }
        buf ^= 1;
    }

    lacc0 += __shfl_xor_sync(0xffffffffu, lacc0, 1);
    lacc0 += __shfl_xor_sync(0xffffffffu, lacc0, 2);
    lacc1 += __shfl_xor_sync(0xffffffffu, lacc1, 1);
    lacc1 += __shfl_xor_sync(0xffffffffu, lacc1, 2);
    if (q == 0) {
        g_pl[unit * 128 + i0] = lacc0;
        g_pl[unit * 128 + i1] = lacc1;
    }

    float* po = &g_po[unit * 8192];
#pragma unroll
    for (int n = 0; n < 8; n++) {
        int col = n * 8 + q * 2;
        *(float2*)&po[i0 * 64 + col] = make_float2(oacc[n][0], oacc[n][1]);
        *(float2*)&po[i1 * 64 + col] = make_float2(oacc[n][2], oacc[n][3]);
    }
}

// ---------------------------------------------------------------------------
// Combine: out = (sum_sp O_sp) / (sum_sp l_sp)
// ---------------------------------------------------------------------------
__global__ __launch_bounds__(128) void combine_kernel(float* __restrict__ out) {
    const int qb = blockIdx.x;
    const int r  = threadIdx.x;
    const int ub = (NQB - 1 - qb) * SPLIT;

    float L = 0.0f;
#pragma unroll
    for (int s = 0; s < SPLIT; s++) L += g_pl[(ub + s) * 128 + r];
    float inv = 1.0f / L;

#pragma unroll
    for (int c4 = 0; c4 < 16; c4++) {
        float4 acc = make_float4(0.f, 0.f, 0.f, 0.f);
#pragma unroll
        for (int s = 0; s < SPLIT; s++) {
            float4 v = *(const float4*)&g_po[(ub + s) * 8192 + r * 64 + c4 * 4];
            acc.x += v.x; acc.y += v.y; acc.z += v.z; acc.w += v.w;
        }
        acc.x *= inv; acc.y *= inv; acc.z *= inv; acc.w *= inv;
        *(float4*)&out[(qb * 128 + r) * HH + c4 * 4] = acc;
    }
}

// ---------------------------------------------------------------------------
extern "C" void kernel_launch(void* const* d_in, const int* in_sizes, int n_in,
                              void* d_out, int out_size) {
    const float* Xq = (const float*)d_in[0];
    const float* Xk = (const float*)d_in[1];
    const float* Xv = (const float*)d_in[2];
    // d_in[3] = mask (causal, implied analytically) -- unused
    const float* Wq = (const float*)d_in[4];
    const float* Wk = (const float*)d_in[5];
    const float* Wv = (const float*)d_in[6];
    float* out = (float*)d_out;

    const int proj_smem = 2 * PSTG * (int)sizeof(float);
    const int attn_smem = 2 * KBUF + 2 * VBUF;
    cudaFuncSetAttribute(proj_mma_kernel,
                         cudaFuncAttributeMaxDynamicSharedMemorySize, proj_smem);
    cudaFuncSetAttribute(attn_mma_kernel,
                         cudaFuncAttributeMaxDynamicSharedMemorySize, attn_smem);

    dim3 pg(TT / 128, 3);
    proj_mma_kernel<<<pg, 256, proj_smem>>>(Xq, Xk, Xv, Wq, Wk, Wv);
    attn_mma_kernel<<<NUNIT, 256, attn_smem>>>();
    combine_kernel<<<NQB, 128>>>(out);
}